// round 3
// baseline (speedup 1.0000x reference)
#include <cuda_runtime.h>

// Problem constants
#define CC      128
#define KP      68                   // padded smem row stride for half-k W tile (floats)
#define KHALF   64
#define GROUPS  8
#define NB      4
#define NN      8192
#define MM      32768
#define KNN     16
#define NROWS   (NB*NN)              // 32768 rows total
#define ROWS_PER_BLK 32
#define THREADS 256
#define CNT_INV (1.0f/131072.0f)     // 1/(N * C/G) = 1/(8192*16)
#define SMEM_BYTES ((ROWS_PER_BLK*CC + CC*KP)*4)   // xs + wt_half = 51200 B

// Scratch (device globals; no cudaMalloc allowed)
__device__ float g_Wt[3][CC*CC];          // transposed weights  Wt[c][k] = W[k][c]
__device__ float g_sum[3][NB*GROUPS];     // per-layer group sums
__device__ float g_sqs[3][NB*GROUPS];     // per-layer group sum-of-squares
__device__ float g_buf0[NROWS*CC];
__device__ float g_buf1[NROWS*CC];

// packed f32x2 FMA (sm_100+): d = a*b + c elementwise on 2 packed floats
__device__ __forceinline__ unsigned long long ffma2(unsigned long long a,
                                                    unsigned long long b,
                                                    unsigned long long c) {
    unsigned long long d;
    asm("fma.rn.f32x2 %0, %1, %2, %3;" : "=l"(d) : "l"(a), "l"(b), "l"(c));
    return d;
}
__device__ __forceinline__ float f2lo(unsigned long long v) {
    return __uint_as_float((unsigned)(v & 0xffffffffULL));
}
__device__ __forceinline__ float f2hi(unsigned long long v) {
    return __uint_as_float((unsigned)(v >> 32));
}
__device__ __forceinline__ float leaky(float h) { return h >= 0.0f ? h : 0.1f * h; }

// ---------------------------------------------------------------------------
// Prep: zero the stats accumulators, transpose W1/W2/W3 into g_Wt
// ---------------------------------------------------------------------------
__global__ void prep_kernel(const float* __restrict__ W1,
                            const float* __restrict__ W2,
                            const float* __restrict__ W3) {
    int idx = blockIdx.x * THREADS + threadIdx.x;
    if (blockIdx.x == 0) {
        int t = threadIdx.x;
        if (t < 96)        { g_sum[t / 32][t % 32] = 0.0f; }
        else if (t < 192)  { int u = t - 96; g_sqs[u / 32][u % 32] = 0.0f; }
    }
    if (idx < 3 * CC * CC) {
        int l = idx / (CC * CC);
        int r = idx % (CC * CC);
        int k = r % CC;              // fast dim -> coalesced store
        int c = r / CC;
        const float* W = (l == 0) ? W1 : ((l == 1) ? W2 : W3);
        g_Wt[l][c * CC + k] = W[k * CC + c];
    }
}

// ---------------------------------------------------------------------------
// Fused layer kernel (32 rows per block, 4 CTAs/SM target).
// MODE 0: input = IDW-weighted KNN gather (layer 1)
// MODE 1: input = leaky(GN(prev_y))                      (layer 2)
// MODE 2: input = leaky(GN(prev_y)) + resid (q_feats)    (layer 3)
// GEMM runs in two k-passes; W^T half-tile staged per pass (smem small ->
// 4 CTAs/SM). Micro-tile per thread: 4 rows x 4 cols, f32x2 packed over k
// parity. Accumulates per-(batch,group) sum / sumsq into g_sum/g_sqs.
// ---------------------------------------------------------------------------
template <int MODE>
__global__ __launch_bounds__(THREADS, 4)
void layer_kernel(const float* __restrict__ in_y,
                  const float* __restrict__ resid,
                  const float* __restrict__ s_feats,
                  const float* __restrict__ q_points,
                  const float* __restrict__ s_points,
                  const int*   __restrict__ nbr_idx,
                  const float* __restrict__ bias,
                  const float* __restrict__ gamma_prev,
                  const float* __restrict__ beta_prev,
                  int layer,
                  float* __restrict__ out_y) {
    extern __shared__ float smem[];
    float* xs = smem;                        // [32][128] input tile
    float* wt = smem + ROWS_PER_BLK * CC;    // [128][KP] half-k W^T tile
    __shared__ float s_ms[GROUPS], s_rs[GROUPS];
    __shared__ float s_gb[2 * CC];
    __shared__ float s_gsum[GROUPS], s_gsqs[GROUPS];

    const int tid  = threadIdx.x;
    const int wid  = tid >> 5;
    const int lane = tid & 31;
    const int row0 = blockIdx.x * ROWS_PER_BLK;  // 32 rows, all one batch
    const int b    = row0 >> 13;                  // /8192

    const float4* Wt4 = (const float4*)(g_Wt[layer]);  // [c][32 float4]

    if (tid < GROUPS) { s_gsum[tid] = 0.0f; s_gsqs[tid] = 0.0f; }

    // Stage W^T k-half 0 (float4 loads, conflict-free stores)
    #pragma unroll
    for (int i = 0; i < 8; i++) {
        int idx = tid + i * THREADS;     // 0..2047
        int c   = idx >> 4;              // 16 float4 per half-row
        int k4  = idx & 15;
        float4 v = Wt4[c * 32 + k4];     // pass 0: k4 offset 0
        *(float4*)&wt[c * KP + k4 * 4] = v;
    }

    // GroupNorm stats of previous layer (MODE != 0)
    if (MODE != 0) {
        if (tid < GROUPS) {
            float s  = g_sum[layer - 1][b * GROUPS + tid];
            float s2 = g_sqs[layer - 1][b * GROUPS + tid];
            float m  = s * CNT_INV;
            float v  = s2 * CNT_INV - m * m;
            s_ms[tid] = m;
            s_rs[tid] = rsqrtf(v + 1e-5f);
        }
        if (tid < CC) { s_gb[tid] = gamma_prev[tid]; s_gb[CC + tid] = beta_prev[tid]; }
    }
    __syncthreads();

    // ---- Stage 1: build xs[32][128] ----
    if (MODE == 0) {
        // one warp per 4 rows; lane owns cols 4*lane..4*lane+3 (float4)
        #pragma unroll
        for (int rr = 0; rr < 4; rr++) {
            int r    = wid * 4 + rr;
            int grow = row0 + r;
            int n    = grow & (NN - 1);
            int base = b * NN + n;
            float qx = q_points[base * 3 + 0];
            float qy = q_points[base * 3 + 1];
            float qz = q_points[base * 3 + 2];
            float wk[KNN];
            float wsum = 0.0f;
            #pragma unroll
            for (int k = 0; k < KNN; k++) {
                const float* sp = s_points + (base * KNN + k) * 3;
                float dx = sp[0] - qx, dy = sp[1] - qy, dz = sp[2] - qz;
                float d2 = dx * dx + dy * dy + dz * dz;
                wk[k] = 1.0f / (d2 + 1e-8f);
                wsum += wk[k];
            }
            float4 acc = make_float4(0.f, 0.f, 0.f, 0.f);
            #pragma unroll
            for (int k = 0; k < KNN; k++) {
                int id = nbr_idx[base * KNN + k];
                const float4* fr = (const float4*)(s_feats + (b * MM + id) * CC);
                float4 v = fr[lane];
                acc.x += wk[k] * v.x; acc.y += wk[k] * v.y;
                acc.z += wk[k] * v.z; acc.w += wk[k] * v.w;
            }
            float inv = 1.0f / wsum;
            acc.x *= inv; acc.y *= inv; acc.z *= inv; acc.w *= inv;
            *(float4*)&xs[r * CC + lane * 4] = acc;
        }
    } else {
        #pragma unroll
        for (int i = 0; i < 4; i++) {
            int f  = tid + i * THREADS;        // float4 index within tile (1024)
            int r  = f >> 5;                   // 32 float4 per row
            int c4 = (f & 31) * 4;
            int g  = c4 >> 4;
            float m = s_ms[g], rs = s_rs[g];
            float4 v = *(const float4*)&in_y[(row0 + r) * CC + c4];
            float4 o;
            o.x = leaky((v.x - m) * rs * s_gb[c4 + 0] + s_gb[CC + c4 + 0]);
            o.y = leaky((v.y - m) * rs * s_gb[c4 + 1] + s_gb[CC + c4 + 1]);
            o.z = leaky((v.z - m) * rs * s_gb[c4 + 2] + s_gb[CC + c4 + 2]);
            o.w = leaky((v.w - m) * rs * s_gb[c4 + 3] + s_gb[CC + c4 + 3]);
            if (MODE == 2) {
                float4 q = *(const float4*)&resid[(row0 + r) * CC + c4];
                o.x += q.x; o.y += q.y; o.z += q.z; o.w += q.w;
            }
            *(float4*)&xs[r * CC + c4] = o;
        }
    }
    __syncthreads();

    // ---- Stage 2: GEMM in two k-passes. Thread tile: rows wid*4..+3,
    // cols lane+32j. f32x2 accumulators hold (even-k, odd-k) partials.
    unsigned long long acc[4][4];
    #pragma unroll
    for (int i = 0; i < 4; i++)
        #pragma unroll
        for (int j = 0; j < 4; j++) acc[i][j] = 0ULL;

    const float* xrow  = xs + wid * 4 * CC;
    const float* wlane = wt + lane * KP;

    #pragma unroll
    for (int pass = 0; pass < 2; pass++) {
        if (pass == 1) {
            __syncthreads();   // everyone done reading half 0
            #pragma unroll
            for (int i = 0; i < 8; i++) {
                int idx = tid + i * THREADS;
                int c   = idx >> 4;
                int k4  = idx & 15;
                float4 v = Wt4[c * 32 + 16 + k4];   // k-half 1
                *(float4*)&wt[c * KP + k4 * 4] = v;
            }
            __syncthreads();
        }
        const int kbase = pass * KHALF;
        #pragma unroll 4
        for (int kq = 0; kq < KHALF / 4; kq++) {
            int k0 = kq * 4;
            ulonglong2 xv[4];
            #pragma unroll
            for (int i = 0; i < 4; i++)
                xv[i] = *(const ulonglong2*)(xrow + i * CC + kbase + k0);
            #pragma unroll
            for (int j = 0; j < 4; j++) {
                ulonglong2 wv = *(const ulonglong2*)(wlane + (32 * j) * KP + k0);
                #pragma unroll
                for (int i = 0; i < 4; i++) {
                    acc[i][j] = ffma2(xv[i].x, wv.x, acc[i][j]);
                    acc[i][j] = ffma2(xv[i].y, wv.y, acc[i][j]);
                }
            }
        }
    }

    // ---- Epilogue: bias, write y, accumulate group stats ----
    #pragma unroll
    for (int j = 0; j < 4; j++) {
        int   c = lane + 32 * j;
        int   g = (lane >> 4) + 2 * j;
        float bj = bias[c];
        float s = 0.0f, s2 = 0.0f;
        #pragma unroll
        for (int i = 0; i < 4; i++) {
            float y = f2lo(acc[i][j]) + f2hi(acc[i][j]) + bj;
            out_y[(row0 + wid * 4 + i) * CC + c] = y;
            s  += y;
            s2 += y * y;
        }
        atomicAdd(&s_gsum[g], s);
        atomicAdd(&s_gsqs[g], s2);
    }
    __syncthreads();
    if (tid < GROUPS) {
        atomicAdd(&g_sum[layer][b * GROUPS + tid], s_gsum[tid]);
        atomicAdd(&g_sqs[layer][b * GROUPS + tid], s_gsqs[tid]);
    }
}

// ---------------------------------------------------------------------------
// Finalize: out = leaky(GN3(y3))
// ---------------------------------------------------------------------------
__global__ void finalize_kernel(const float* __restrict__ in_y,
                                const float* __restrict__ gamma,
                                const float* __restrict__ beta,
                                float* __restrict__ out) {
    int f  = blockIdx.x * blockDim.x + threadIdx.x;   // float4 index
    int e  = f * 4;
    int c4 = e & (CC - 1);
    int row = e >> 7;
    int b  = row >> 13;
    int g  = c4 >> 4;
    float s  = g_sum[2][b * GROUPS + g];
    float s2 = g_sqs[2][b * GROUPS + g];
    float m  = s * CNT_INV;
    float v  = s2 * CNT_INV - m * m;
    float rs = rsqrtf(v + 1e-5f);
    float4 x = *(const float4*)&in_y[e];
    float4 o;
    o.x = leaky((x.x - m) * rs * gamma[c4 + 0] + beta[c4 + 0]);
    o.y = leaky((x.y - m) * rs * gamma[c4 + 1] + beta[c4 + 1]);
    o.z = leaky((x.z - m) * rs * gamma[c4 + 2] + beta[c4 + 2]);
    o.w = leaky((x.w - m) * rs * gamma[c4 + 3] + beta[c4 + 3]);
    *(float4*)&out[e] = o;
}

// ---------------------------------------------------------------------------
extern "C" void kernel_launch(void* const* d_in, const int* in_sizes, int n_in,
                              void* d_out, int out_size) {
    const float* q_feats  = (const float*)d_in[0];
    const float* s_feats  = (const float*)d_in[1];
    const float* q_points = (const float*)d_in[2];
    const float* s_points = (const float*)d_in[3];
    const int*   nbr_idx  = (const int*)  d_in[4];
    const float* W1 = (const float*)d_in[5];
    const float* b1 = (const float*)d_in[6];
    const float* g1 = (const float*)d_in[7];
    const float* be1 = (const float*)d_in[8];
    const float* W2 = (const float*)d_in[9];
    const float* b2 = (const float*)d_in[10];
    const float* g2 = (const float*)d_in[11];
    const float* be2 = (const float*)d_in[12];
    const float* W3 = (const float*)d_in[13];
    const float* b3 = (const float*)d_in[14];
    const float* g3 = (const float*)d_in[15];
    const float* be3 = (const float*)d_in[16];
    float* out = (float*)d_out;

    float *buf0 = nullptr, *buf1 = nullptr;
    cudaGetSymbolAddress((void**)&buf0, g_buf0);
    cudaGetSymbolAddress((void**)&buf1, g_buf1);

    cudaFuncSetAttribute(layer_kernel<0>, cudaFuncAttributeMaxDynamicSharedMemorySize, SMEM_BYTES);
    cudaFuncSetAttribute(layer_kernel<1>, cudaFuncAttributeMaxDynamicSharedMemorySize, SMEM_BYTES);
    cudaFuncSetAttribute(layer_kernel<2>, cudaFuncAttributeMaxDynamicSharedMemorySize, SMEM_BYTES);

    prep_kernel<<<(3 * CC * CC + THREADS - 1) / THREADS, THREADS>>>(W1, W2, W3);

    const int nblk = NROWS / ROWS_PER_BLK;   // 1024
    layer_kernel<0><<<nblk, THREADS, SMEM_BYTES>>>(
        nullptr, nullptr, s_feats, q_points, s_points, nbr_idx,
        b1, nullptr, nullptr, 0, buf0);
    layer_kernel<1><<<nblk, THREADS, SMEM_BYTES>>>(
        buf0, nullptr, nullptr, nullptr, nullptr, nullptr,
        b2, g1, be1, 1, buf1);
    layer_kernel<2><<<nblk, THREADS, SMEM_BYTES>>>(
        buf1, q_feats, nullptr, nullptr, nullptr, nullptr,
        b3, g2, be2, 2, buf0);
    finalize_kernel<<<(NROWS * CC / 4) / THREADS, THREADS>>>(buf0, g3, be3, out);
}

// round 5
// speedup vs baseline: 1.8854x; 1.8854x over previous
#include <cuda_runtime.h>
#include <cuda_bf16.h>
#include <cstdint>

// Problem constants
#define CC      128
#define GROUPS  8
#define NB      4
#define NN      8192
#define MM      32768
#define KNN     16
#define NROWS   (NB*NN)
#define TROWS   64                   // rows per CTA tile
#define THREADS 256
#define CNT_INV (1.0f/131072.0f)
#define APAD    136                  // padded bf16 row stride (272B -> conflict-free ldmatrix)

// smem byte offsets (dynamic region, 16B aligned)
#define SM_AH   0
#define SM_AL   (TROWS*APAD*2)             // 17408
#define SM_BH   (2*TROWS*APAD*2)           // 34816
#define SM_BL   (SM_BH + CC*APAD*2)        // 69632
#define SMEM_DYN (SM_BL + CC*APAD*2)       // 104448

// Scratch (device globals; no cudaMalloc allowed)
__device__ __align__(16) __nv_bfloat16 g_Wbf[3][2][CC*CC]; // [layer][hi/lo][n*CC+k]
__device__ float g_sum[3][NB*GROUPS];
__device__ float g_sqs[3][NB*GROUPS];
__device__ float g_buf0[NROWS*CC];
__device__ float g_buf1[NROWS*CC];

// ---------------------------------------------------------------------------
// Helpers (all plain sm_80+ features; NO 'a'-gated instructions)
// ---------------------------------------------------------------------------
__device__ __forceinline__ uint32_t cvta_smem(const void* p) {
    uint32_t a;
    asm("{ .reg .u64 t; cvta.to.shared.u64 t, %1; cvt.u32.u64 %0, t; }"
        : "=r"(a) : "l"(p));
    return a;
}
__device__ __forceinline__ void ldmx4(uint32_t addr, uint32_t r[4]) {
    asm volatile("ldmatrix.sync.aligned.m8n8.x4.shared.b16 {%0,%1,%2,%3}, [%4];"
        : "=r"(r[0]), "=r"(r[1]), "=r"(r[2]), "=r"(r[3]) : "r"(addr));
}
__device__ __forceinline__ void mma16816(float d[4], const uint32_t a[4],
                                         const uint32_t b[2]) {
    asm volatile(
        "mma.sync.aligned.m16n8k16.row.col.f32.bf16.bf16.f32 "
        "{%0,%1,%2,%3}, {%4,%5,%6,%7}, {%8,%9}, {%0,%1,%2,%3};"
        : "+f"(d[0]), "+f"(d[1]), "+f"(d[2]), "+f"(d[3])
        : "r"(a[0]), "r"(a[1]), "r"(a[2]), "r"(a[3]), "r"(b[0]), "r"(b[1]));
}
#define STS64(a, x, y) \
    asm volatile("st.shared.v2.b32 [%0], {%1,%2};" :: "r"(a), "r"(x), "r"(y) : "memory")
#define STS128(a, v) \
    asm volatile("st.shared.v4.b32 [%0], {%1,%2,%3,%4};" \
                 :: "r"(a), "r"((v).x), "r"((v).y), "r"((v).z), "r"((v).w) : "memory")

__device__ __forceinline__ float leaky(float h) { return h >= 0.0f ? h : 0.1f * h; }

// ---------------------------------------------------------------------------
// Prep: zero stats, build bf16 hi/lo split of W^T (Wbf[n][k] = W[k][n])
// ---------------------------------------------------------------------------
__global__ void prep_kernel(const float* __restrict__ W1,
                            const float* __restrict__ W2,
                            const float* __restrict__ W3) {
    int idx = blockIdx.x * THREADS + threadIdx.x;
    if (blockIdx.x == 0) {
        int t = threadIdx.x;
        if (t < 96)        { g_sum[t / 32][t % 32] = 0.0f; }
        else if (t < 192)  { int u = t - 96; g_sqs[u / 32][u % 32] = 0.0f; }
    }
    if (idx < 3 * CC * CC) {
        int l = idx / (CC * CC);
        int r = idx % (CC * CC);
        int k = r % CC;
        int c = r / CC;              // output channel n
        const float* W = (l == 0) ? W1 : ((l == 1) ? W2 : W3);
        float v = W[k * CC + c];
        __nv_bfloat16 hi = __float2bfloat16(v);
        __nv_bfloat16 lo = __float2bfloat16(v - __bfloat162float(hi));
        g_Wbf[l][0][c * CC + k] = hi;
        g_Wbf[l][1][c * CC + k] = lo;
    }
}

// ---------------------------------------------------------------------------
// Fused layer kernel: 64-row tile, HMMA bf16 3-term-split GEMM.
// MODE 0: x = IDW-weighted KNN gather
// MODE 1: x = leaky(GN(prev_y))
// MODE 2: x = leaky(GN(prev_y)) + resid
// y = x @ W + b -> out_y; accumulates group sum/sumsq for this layer's GN.
// ---------------------------------------------------------------------------
template <int MODE>
__global__ __launch_bounds__(THREADS)
void layer_kernel(const float* __restrict__ in_y,
                  const float* __restrict__ resid,
                  const float* __restrict__ s_feats,
                  const float* __restrict__ q_points,
                  const float* __restrict__ s_points,
                  const int*   __restrict__ nbr_idx,
                  const float* __restrict__ bias,
                  const float* __restrict__ gamma_prev,
                  const float* __restrict__ beta_prev,
                  int layer,
                  float* __restrict__ out_y) {
    extern __shared__ __align__(16) char smem[];
    __shared__ float s_ms[GROUPS], s_rs[GROUPS];
    __shared__ float s_gb[2 * CC];
    __shared__ float s_gsum[GROUPS], s_gsqs[GROUPS];

    const int tid  = threadIdx.x;
    const int wid  = tid >> 5;
    const int lane = tid & 31;
    const int row0 = blockIdx.x * TROWS;
    const int b    = row0 >> 13;

    const uint32_t sb = cvta_smem(smem);

    if (tid < GROUPS) { s_gsum[tid] = 0.0f; s_gsqs[tid] = 0.0f; }

    // GroupNorm stats + gamma/beta of previous layer
    if (MODE != 0) {
        if (tid < GROUPS) {
            float s  = g_sum[layer - 1][b * GROUPS + tid];
            float s2 = g_sqs[layer - 1][b * GROUPS + tid];
            float m  = s * CNT_INV;
            float v  = s2 * CNT_INV - m * m;
            s_ms[tid] = m;
            s_rs[tid] = rsqrtf(v + 1e-5f);
        }
        if (tid < CC) { s_gb[tid] = gamma_prev[tid]; s_gb[CC + tid] = beta_prev[tid]; }
        __syncthreads();
    }

    // ---- Stage B: Wh/Wl bf16 -> smem, padded stride APAD ----
    #pragma unroll
    for (int t = 0; t < 8; t++) {
        int idx = tid + t * THREADS;        // 0..2047 chunks of 8 bf16
        int n   = idx >> 4;
        int k0  = (idx & 15) * 8;
        uint32_t off = (uint32_t)(n * APAD + k0) * 2;
        uint4 vh = *(const uint4*)&g_Wbf[layer][0][n * CC + k0];
        uint4 vl = *(const uint4*)&g_Wbf[layer][1][n * CC + k0];
        STS128(sb + SM_BH + off, vh);
        STS128(sb + SM_BL + off, vl);
    }

    // ---- Stage A: build x rows, split bf16 hi/lo, store (stride APAD) ----
    #pragma unroll
    for (int it = 0; it < 8; it++) {
        int r, c4;
        float4 x;
        if (MODE == 0) {
            r  = wid * 8 + it;              // warp owns 8 rows
            c4 = lane * 4;                  // lane owns col quad
            int n    = (row0 + r) & (NN - 1);
            int base = b * NN + n;
            float qx = q_points[base * 3 + 0];
            float qy = q_points[base * 3 + 1];
            float qz = q_points[base * 3 + 2];
            float wk[KNN];
            float wsum = 0.0f;
            #pragma unroll
            for (int k = 0; k < KNN; k++) {
                const float* sp = s_points + (base * KNN + k) * 3;
                float dx = sp[0] - qx, dy = sp[1] - qy, dz = sp[2] - qz;
                float d2 = dx * dx + dy * dy + dz * dz;
                wk[k] = 1.0f / (d2 + 1e-8f);
                wsum += wk[k];
            }
            x = make_float4(0.f, 0.f, 0.f, 0.f);
            #pragma unroll
            for (int k = 0; k < KNN; k++) {
                int id = nbr_idx[base * KNN + k];
                const float4* fr = (const float4*)(s_feats + ((size_t)(b * MM + id)) * CC);
                float4 v = fr[lane];
                x.x += wk[k] * v.x; x.y += wk[k] * v.y;
                x.z += wk[k] * v.z; x.w += wk[k] * v.w;
            }
            float inv = 1.0f / wsum;
            x.x *= inv; x.y *= inv; x.z *= inv; x.w *= inv;
        } else {
            int f = tid + it * THREADS;     // 2048 col-quads in tile
            r  = f >> 5;
            c4 = (f & 31) * 4;
            int g = c4 >> 4;
            float m = s_ms[g], rs = s_rs[g];
            float4 v = *(const float4*)&in_y[(size_t)(row0 + r) * CC + c4];
            x.x = leaky((v.x - m) * rs * s_gb[c4 + 0] + s_gb[CC + c4 + 0]);
            x.y = leaky((v.y - m) * rs * s_gb[c4 + 1] + s_gb[CC + c4 + 1]);
            x.z = leaky((v.z - m) * rs * s_gb[c4 + 2] + s_gb[CC + c4 + 2]);
            x.w = leaky((v.w - m) * rs * s_gb[c4 + 3] + s_gb[CC + c4 + 3]);
            if (MODE == 2) {
                float4 q = *(const float4*)&resid[(size_t)(row0 + r) * CC + c4];
                x.x += q.x; x.y += q.y; x.z += q.z; x.w += q.w;
            }
        }
        __nv_bfloat16 h0 = __float2bfloat16(x.x);
        __nv_bfloat16 h1 = __float2bfloat16(x.y);
        __nv_bfloat16 h2 = __float2bfloat16(x.z);
        __nv_bfloat16 h3 = __float2bfloat16(x.w);
        __nv_bfloat16 l0 = __float2bfloat16(x.x - __bfloat162float(h0));
        __nv_bfloat16 l1 = __float2bfloat16(x.y - __bfloat162float(h1));
        __nv_bfloat16 l2 = __float2bfloat16(x.z - __bfloat162float(h2));
        __nv_bfloat16 l3 = __float2bfloat16(x.w - __bfloat162float(h3));
        uint32_t ha = (uint32_t)__bfloat16_as_ushort(h0) | ((uint32_t)__bfloat16_as_ushort(h1) << 16);
        uint32_t hb = (uint32_t)__bfloat16_as_ushort(h2) | ((uint32_t)__bfloat16_as_ushort(h3) << 16);
        uint32_t la = (uint32_t)__bfloat16_as_ushort(l0) | ((uint32_t)__bfloat16_as_ushort(l1) << 16);
        uint32_t lb = (uint32_t)__bfloat16_as_ushort(l2) | ((uint32_t)__bfloat16_as_ushort(l3) << 16);
        uint32_t off = (uint32_t)(r * APAD + c4) * 2;
        STS64(sb + SM_AH + off, ha, hb);
        STS64(sb + SM_AL + off, la, lb);
    }
    __syncthreads();

    // ---- HMMA GEMM: warp tile m16 x n64, 3-term split ----
    const int mbase = (wid & 3) * 16;
    const int nbase = (wid >> 2) * 64;

    float acc[8][4];
    #pragma unroll
    for (int j = 0; j < 8; j++)
        #pragma unroll
        for (int q = 0; q < 4; q++) acc[j][q] = 0.0f;

    // ldmatrix lane-address bases (rowgroup layout per PTX m8n8.x4 spec)
    const uint32_t aoff = sb + SM_AH +
        (uint32_t)(((mbase + (lane & 15)) * APAD + ((lane >> 4) << 3)) << 1);
    const uint32_t boff = sb + SM_BH +
        (uint32_t)((((nbase + (lane & 7) + ((lane >> 4) << 3)) * APAD) + (lane & 8)) << 1);

    #pragma unroll
    for (int t = 0; t < 8; t++) {
        const uint32_t ka = (uint32_t)t * 32;   // 16 bf16 = 32B per k-step
        uint32_t ah[4], al[4];
        ldmx4(aoff + ka, ah);
        ldmx4(aoff + ka + (SM_AL - SM_AH), al);
        #pragma unroll
        for (int p = 0; p < 4; p++) {
            uint32_t ba = boff + ka + (uint32_t)p * (16 * APAD * 2);
            uint32_t bh[4], bl[4];
            ldmx4(ba, bh);
            ldmx4(ba + (SM_BL - SM_BH), bl);
            mma16816(acc[2 * p],     ah, &bh[0]);
            mma16816(acc[2 * p],     al, &bh[0]);
            mma16816(acc[2 * p],     ah, &bl[0]);
            mma16816(acc[2 * p + 1], ah, &bh[2]);
            mma16816(acc[2 * p + 1], al, &bh[2]);
            mma16816(acc[2 * p + 1], ah, &bl[2]);
        }
    }

    // ---- Epilogue: bias + store from fragments, warp-reduced stats ----
    {
        const int r0g = row0 + mbase + (lane >> 2);
        #pragma unroll
        for (int j = 0; j < 8; j++) {
            int c  = nbase + 8 * j + (lane & 3) * 2;
            float bb0 = __ldg(&bias[c]);
            float bb1 = __ldg(&bias[c + 1]);
            float y00 = acc[j][0] + bb0;
            float y01 = acc[j][1] + bb1;
            float y10 = acc[j][2] + bb0;
            float y11 = acc[j][3] + bb1;
            *(float2*)&out_y[(size_t)r0g * CC + c]       = make_float2(y00, y01);
            *(float2*)&out_y[(size_t)(r0g + 8) * CC + c] = make_float2(y10, y11);
            float s  = y00 + y01 + y10 + y11;
            float s2 = y00 * y00 + y01 * y01 + y10 * y10 + y11 * y11;
            #pragma unroll
            for (int o = 16; o > 0; o >>= 1) {
                s  += __shfl_xor_sync(0xffffffffu, s,  o);
                s2 += __shfl_xor_sync(0xffffffffu, s2, o);
            }
            if (lane == 0) {
                int g = (nbase + 8 * j) >> 4;
                atomicAdd(&s_gsum[g], s);
                atomicAdd(&s_gsqs[g], s2);
            }
        }
    }
    __syncthreads();
    if (tid < GROUPS) {
        atomicAdd(&g_sum[layer][b * GROUPS + tid], s_gsum[tid]);
        atomicAdd(&g_sqs[layer][b * GROUPS + tid], s_gsqs[tid]);
    }
}

// ---------------------------------------------------------------------------
// Finalize: out = leaky(GN3(y3))
// ---------------------------------------------------------------------------
__global__ void finalize_kernel(const float* __restrict__ in_y,
                                const float* __restrict__ gamma,
                                const float* __restrict__ beta,
                                float* __restrict__ out) {
    int f  = blockIdx.x * blockDim.x + threadIdx.x;
    int e  = f * 4;
    int c4 = e & (CC - 1);
    int row = e >> 7;
    int b  = row >> 13;
    int g  = c4 >> 4;
    float s  = g_sum[2][b * GROUPS + g];
    float s2 = g_sqs[2][b * GROUPS + g];
    float m  = s * CNT_INV;
    float v  = s2 * CNT_INV - m * m;
    float rs = rsqrtf(v + 1e-5f);
    float4 x = *(const float4*)&in_y[e];
    float4 o;
    o.x = leaky((x.x - m) * rs * gamma[c4 + 0] + beta[c4 + 0]);
    o.y = leaky((x.y - m) * rs * gamma[c4 + 1] + beta[c4 + 1]);
    o.z = leaky((x.z - m) * rs * gamma[c4 + 2] + beta[c4 + 2]);
    o.w = leaky((x.w - m) * rs * gamma[c4 + 3] + beta[c4 + 3]);
    *(float4*)&out[e] = o;
}

// ---------------------------------------------------------------------------
extern "C" void kernel_launch(void* const* d_in, const int* in_sizes, int n_in,
                              void* d_out, int out_size) {
    const float* q_feats  = (const float*)d_in[0];
    const float* s_feats  = (const float*)d_in[1];
    const float* q_points = (const float*)d_in[2];
    const float* s_points = (const float*)d_in[3];
    const int*   nbr_idx  = (const int*)  d_in[4];
    const float* W1 = (const float*)d_in[5];
    const float* b1 = (const float*)d_in[6];
    const float* g1 = (const float*)d_in[7];
    const float* be1 = (const float*)d_in[8];
    const float* W2 = (const float*)d_in[9];
    const float* b2 = (const float*)d_in[10];
    const float* g2 = (const float*)d_in[11];
    const float* be2 = (const float*)d_in[12];
    const float* W3 = (const float*)d_in[13];
    const float* b3 = (const float*)d_in[14];
    const float* g3 = (const float*)d_in[15];
    const float* be3 = (const float*)d_in[16];
    float* out = (float*)d_out;

    float *buf0 = nullptr, *buf1 = nullptr;
    cudaGetSymbolAddress((void**)&buf0, g_buf0);
    cudaGetSymbolAddress((void**)&buf1, g_buf1);

    cudaFuncSetAttribute(layer_kernel<0>, cudaFuncAttributeMaxDynamicSharedMemorySize, SMEM_DYN);
    cudaFuncSetAttribute(layer_kernel<1>, cudaFuncAttributeMaxDynamicSharedMemorySize, SMEM_DYN);
    cudaFuncSetAttribute(layer_kernel<2>, cudaFuncAttributeMaxDynamicSharedMemorySize, SMEM_DYN);

    prep_kernel<<<(3 * CC * CC + THREADS - 1) / THREADS, THREADS>>>(W1, W2, W3);

    const int nblk = NROWS / TROWS;   // 512
    layer_kernel<0><<<nblk, THREADS, SMEM_DYN>>>(
        nullptr, nullptr, s_feats, q_points, s_points, nbr_idx,
        b1, nullptr, nullptr, 0, buf0);
    layer_kernel<1><<<nblk, THREADS, SMEM_DYN>>>(
        buf0, nullptr, nullptr, nullptr, nullptr, nullptr,
        b2, g1, be1, 1, buf1);
    layer_kernel<2><<<nblk, THREADS, SMEM_DYN>>>(
        buf1, q_feats, nullptr, nullptr, nullptr, nullptr,
        b3, g2, be2, 2, buf0);
    finalize_kernel<<<(NROWS * CC / 4) / THREADS, THREADS>>>(buf0, g3, be3, out);
}

// round 6
// speedup vs baseline: 2.1104x; 1.1193x over previous
#include <cuda_runtime.h>
#include <cuda_bf16.h>
#include <cstdint>

// Problem constants
#define CC      128
#define GROUPS  8
#define NB      4
#define NN      8192
#define MM      32768
#define KNN     16
#define NROWS   (NB*NN)
#define TROWS   64                   // rows per CTA tile
#define THREADS 256
#define CNT_INV (1.0f/131072.0f)
#define APAD    136                  // padded bf16 row stride (272B -> conflict-free ldmatrix)

// layer-kernel smem: A tiles only
#define SM_AH   0
#define SM_AL   (TROWS*APAD*2)             // 17408
#define SMEM_DYN (2*TROWS*APAD*2)          // 34816

// prep2 smem: one 128xAPAD bf16 tile
#define SMEM_P2 (CC*APAD*2)                // 34816

// Scratch (device globals; no cudaMalloc allowed)
__device__ __align__(16) __nv_bfloat16 g_Wbf[3][2][CC*CC]; // [layer][hi/lo][n*CC+k]
__device__ __align__(16) uint4 g_Wfrag[3][2][8][8][32];    // [layer][hi/lo][t][nb16][lane]
__device__ float g_sum[3][NB*GROUPS];
__device__ float g_sqs[3][NB*GROUPS];
__device__ float g_buf0[NROWS*CC];
__device__ float g_buf1[NROWS*CC];

// ---------------------------------------------------------------------------
// Helpers (all plain sm_80+ features; NO 'a'-gated instructions)
// ---------------------------------------------------------------------------
__device__ __forceinline__ uint32_t cvta_smem(const void* p) {
    uint32_t a;
    asm("{ .reg .u64 t; cvta.to.shared.u64 t, %1; cvt.u32.u64 %0, t; }"
        : "=r"(a) : "l"(p));
    return a;
}
__device__ __forceinline__ void ldmx4(uint32_t addr, uint32_t r[4]) {
    asm volatile("ldmatrix.sync.aligned.m8n8.x4.shared.b16 {%0,%1,%2,%3}, [%4];"
        : "=r"(r[0]), "=r"(r[1]), "=r"(r[2]), "=r"(r[3]) : "r"(addr));
}
__device__ __forceinline__ void mma16816(float d[4], const uint32_t a[4],
                                         uint32_t b0, uint32_t b1) {
    asm volatile(
        "mma.sync.aligned.m16n8k16.row.col.f32.bf16.bf16.f32 "
        "{%0,%1,%2,%3}, {%4,%5,%6,%7}, {%8,%9}, {%0,%1,%2,%3};"
        : "+f"(d[0]), "+f"(d[1]), "+f"(d[2]), "+f"(d[3])
        : "r"(a[0]), "r"(a[1]), "r"(a[2]), "r"(a[3]), "r"(b0), "r"(b1));
}
#define STS64(a, x, y) \
    asm volatile("st.shared.v2.b32 [%0], {%1,%2};" :: "r"(a), "r"(x), "r"(y) : "memory")
#define STS128(a, v) \
    asm volatile("st.shared.v4.b32 [%0], {%1,%2,%3,%4};" \
                 :: "r"(a), "r"((v).x), "r"((v).y), "r"((v).z), "r"((v).w) : "memory")

__device__ __forceinline__ float leaky(float h) { return h >= 0.0f ? h : 0.1f * h; }

// ---------------------------------------------------------------------------
// prep1: zero stats, build bf16 hi/lo split of W^T (Wbf[n][k] = W[k][n])
// ---------------------------------------------------------------------------
__global__ void prep1_kernel(const float* __restrict__ W1,
                             const float* __restrict__ W2,
                             const float* __restrict__ W3) {
    int idx = blockIdx.x * THREADS + threadIdx.x;
    if (blockIdx.x == 0) {
        int t = threadIdx.x;
        if (t < 96)        { g_sum[t / 32][t % 32] = 0.0f; }
        else if (t < 192)  { int u = t - 96; g_sqs[u / 32][u % 32] = 0.0f; }
    }
    if (idx < 3 * CC * CC) {
        int l = idx / (CC * CC);
        int r = idx % (CC * CC);
        int k = r % CC;
        int c = r / CC;              // output channel n
        const float* W = (l == 0) ? W1 : ((l == 1) ? W2 : W3);
        float v = W[k * CC + c];
        __nv_bfloat16 hi = __float2bfloat16(v);
        __nv_bfloat16 lo = __float2bfloat16(v - __bfloat162float(hi));
        g_Wbf[l][0][c * CC + k] = hi;
        g_Wbf[l][1][c * CC + k] = lo;
    }
}

// ---------------------------------------------------------------------------
// prep2: fragmentize W via the exact ldmatrix sequence the layer kernel used.
// Block (l, h) = (blockIdx.x >> 1, blockIdx.x & 1). 6 blocks total.
// ---------------------------------------------------------------------------
__global__ void prep2_kernel() {
    extern __shared__ __align__(16) char smem[];
    const int tid  = threadIdx.x;
    const int wid  = tid >> 5;
    const int lane = tid & 31;
    const int l = blockIdx.x >> 1;
    const int h = blockIdx.x & 1;
    const uint32_t sb = cvta_smem(smem);

    // stage 128xAPAD bf16 tile
    #pragma unroll
    for (int t = 0; t < 8; t++) {
        int idx = tid + t * THREADS;        // 2048 chunks of 8 bf16
        int n   = idx >> 4;
        int k0  = (idx & 15) * 8;
        uint4 v = *(const uint4*)&g_Wbf[l][h][n * CC + k0];
        STS128(sb + (uint32_t)(n * APAD + k0) * 2, v);
    }
    __syncthreads();

    // 64 jobs: (t, nb16); 8 per warp. Same lane addressing as the GEMM used.
    const uint32_t lrow = (uint32_t)((lane & 7) + ((lane >> 4) << 3));
    const uint32_t lcol = (uint32_t)(lane & 8) << 1;
    #pragma unroll
    for (int i = 0; i < 8; i++) {
        int job  = wid * 8 + i;
        int t    = job & 7;
        int nb   = job >> 3;
        uint32_t addr = sb + (((uint32_t)(nb * 16) + lrow) * APAD) * 2 + lcol
                      + (uint32_t)t * 32;
        uint32_t r[4];
        ldmx4(addr, r);
        g_Wfrag[l][h][t][nb][lane] = make_uint4(r[0], r[1], r[2], r[3]);
    }
}

// ---------------------------------------------------------------------------
// Fused layer kernel: 64-row tile, HMMA bf16 3-term-split GEMM.
// B comes from precomputed register fragments in global (L1-shared across CTAs).
// MODE 0: x = IDW gather   MODE 1: x = leaky(GN(prev))   MODE 2: +resid
// ---------------------------------------------------------------------------
template <int MODE>
__global__ __launch_bounds__(THREADS, 3)
void layer_kernel(const float* __restrict__ in_y,
                  const float* __restrict__ resid,
                  const float* __restrict__ s_feats,
                  const float* __restrict__ q_points,
                  const float* __restrict__ s_points,
                  const int*   __restrict__ nbr_idx,
                  const float* __restrict__ bias,
                  const float* __restrict__ gamma_prev,
                  const float* __restrict__ beta_prev,
                  int layer,
                  float* __restrict__ out_y) {
    extern __shared__ __align__(16) char smem[];
    __shared__ float s_ms[GROUPS], s_rs[GROUPS];
    __shared__ float s_gb[2 * CC];
    __shared__ float s_gsum[GROUPS], s_gsqs[GROUPS];

    const int tid  = threadIdx.x;
    const int wid  = tid >> 5;
    const int lane = tid & 31;
    const int row0 = blockIdx.x * TROWS;
    const int b    = row0 >> 13;

    const uint32_t sb = cvta_smem(smem);

    if (tid < GROUPS) { s_gsum[tid] = 0.0f; s_gsqs[tid] = 0.0f; }

    if (MODE != 0) {
        if (tid < GROUPS) {
            float s  = g_sum[layer - 1][b * GROUPS + tid];
            float s2 = g_sqs[layer - 1][b * GROUPS + tid];
            float m  = s * CNT_INV;
            float v  = s2 * CNT_INV - m * m;
            s_ms[tid] = m;
            s_rs[tid] = rsqrtf(v + 1e-5f);
        }
        if (tid < CC) { s_gb[tid] = gamma_prev[tid]; s_gb[CC + tid] = beta_prev[tid]; }
        __syncthreads();
    }

    // ---- Stage A: build x rows, split bf16 hi/lo, store (stride APAD) ----
    #pragma unroll
    for (int it = 0; it < 8; it++) {
        int r, c4;
        float4 x;
        if (MODE == 0) {
            r  = wid * 8 + it;
            c4 = lane * 4;
            int n    = (row0 + r) & (NN - 1);
            int base = b * NN + n;
            float qx = q_points[base * 3 + 0];
            float qy = q_points[base * 3 + 1];
            float qz = q_points[base * 3 + 2];
            float wk[KNN];
            float wsum = 0.0f;
            #pragma unroll
            for (int k = 0; k < KNN; k++) {
                const float* sp = s_points + (base * KNN + k) * 3;
                float dx = sp[0] - qx, dy = sp[1] - qy, dz = sp[2] - qz;
                float d2 = dx * dx + dy * dy + dz * dz;
                wk[k] = 1.0f / (d2 + 1e-8f);
                wsum += wk[k];
            }
            x = make_float4(0.f, 0.f, 0.f, 0.f);
            #pragma unroll
            for (int k = 0; k < KNN; k++) {
                int id = nbr_idx[base * KNN + k];
                const float4* fr = (const float4*)(s_feats + ((size_t)(b * MM + id)) * CC);
                float4 v = fr[lane];
                x.x += wk[k] * v.x; x.y += wk[k] * v.y;
                x.z += wk[k] * v.z; x.w += wk[k] * v.w;
            }
            float inv = 1.0f / wsum;
            x.x *= inv; x.y *= inv; x.z *= inv; x.w *= inv;
        } else {
            int f = tid + it * THREADS;
            r  = f >> 5;
            c4 = (f & 31) * 4;
            int g = c4 >> 4;
            float m = s_ms[g], rs = s_rs[g];
            float4 v = *(const float4*)&in_y[(size_t)(row0 + r) * CC + c4];
            x.x = leaky((v.x - m) * rs * s_gb[c4 + 0] + s_gb[CC + c4 + 0]);
            x.y = leaky((v.y - m) * rs * s_gb[c4 + 1] + s_gb[CC + c4 + 1]);
            x.z = leaky((v.z - m) * rs * s_gb[c4 + 2] + s_gb[CC + c4 + 2]);
            x.w = leaky((v.w - m) * rs * s_gb[c4 + 3] + s_gb[CC + c4 + 3]);
            if (MODE == 2) {
                float4 q = *(const float4*)&resid[(size_t)(row0 + r) * CC + c4];
                x.x += q.x; x.y += q.y; x.z += q.z; x.w += q.w;
            }
        }
        __nv_bfloat16 h0 = __float2bfloat16(x.x);
        __nv_bfloat16 h1 = __float2bfloat16(x.y);
        __nv_bfloat16 h2 = __float2bfloat16(x.z);
        __nv_bfloat16 h3 = __float2bfloat16(x.w);
        __nv_bfloat16 l0 = __float2bfloat16(x.x - __bfloat162float(h0));
        __nv_bfloat16 l1 = __float2bfloat16(x.y - __bfloat162float(h1));
        __nv_bfloat16 l2 = __float2bfloat16(x.z - __bfloat162float(h2));
        __nv_bfloat16 l3 = __float2bfloat16(x.w - __bfloat162float(h3));
        uint32_t ha = (uint32_t)__bfloat16_as_ushort(h0) | ((uint32_t)__bfloat16_as_ushort(h1) << 16);
        uint32_t hb = (uint32_t)__bfloat16_as_ushort(h2) | ((uint32_t)__bfloat16_as_ushort(h3) << 16);
        uint32_t la = (uint32_t)__bfloat16_as_ushort(l0) | ((uint32_t)__bfloat16_as_ushort(l1) << 16);
        uint32_t lb = (uint32_t)__bfloat16_as_ushort(l2) | ((uint32_t)__bfloat16_as_ushort(l3) << 16);
        uint32_t off = (uint32_t)(r * APAD + c4) * 2;
        STS64(sb + SM_AH + off, ha, hb);
        STS64(sb + SM_AL + off, la, lb);
    }
    __syncthreads();

    // ---- HMMA GEMM: warp tile m16 x n64, 3-term split; B frags via LDG ----
    const int mbase = (wid & 3) * 16;
    const int nb0   = (wid >> 2) * 4;     // first n16 fragment index

    float acc[8][4];
    #pragma unroll
    for (int j = 0; j < 8; j++)
        #pragma unroll
        for (int q = 0; q < 4; q++) acc[j][q] = 0.0f;

    const uint32_t aoff = sb + SM_AH +
        (uint32_t)(((mbase + (lane & 15)) * APAD + ((lane >> 4) << 3)) << 1);

    const uint4* __restrict__ wfh = &g_Wfrag[layer][0][0][0][lane];
    const uint4* __restrict__ wfl = &g_Wfrag[layer][1][0][0][lane];

    #pragma unroll
    for (int t = 0; t < 8; t++) {
        const uint32_t ka = (uint32_t)t * 32;
        uint32_t ah[4], al[4];
        ldmx4(aoff + ka, ah);
        ldmx4(aoff + ka + SM_AL, al);
        #pragma unroll
        for (int p = 0; p < 4; p++) {
            const int fidx = (t * 8 + nb0 + p) * 32;
            uint4 bh = __ldg(wfh + fidx);
            uint4 bl = __ldg(wfl + fidx);
            float* a0 = acc[2 * p];
            float* a1 = acc[2 * p + 1];
            mma16816(a0, ah, bh.x, bh.y);
            mma16816(a0, al, bh.x, bh.y);
            mma16816(a0, ah, bl.x, bl.y);
            mma16816(a1, ah, bh.z, bh.w);
            mma16816(a1, al, bh.z, bh.w);
            mma16816(a1, ah, bl.z, bl.w);
        }
    }

    // ---- Epilogue: bias + store from fragments, warp-reduced stats ----
    {
        const int r0g   = row0 + mbase + (lane >> 2);
        const int nbase = (wid >> 2) * 64;
        #pragma unroll
        for (int gj = 0; gj < 4; gj++) {
            float s = 0.0f, s2 = 0.0f;
            #pragma unroll
            for (int jj = 0; jj < 2; jj++) {
                int j = 2 * gj + jj;
                int c = nbase + 8 * j + (lane & 3) * 2;
                float bb0 = __ldg(&bias[c]);
                float bb1 = __ldg(&bias[c + 1]);
                float y00 = acc[j][0] + bb0;
                float y01 = acc[j][1] + bb1;
                float y10 = acc[j][2] + bb0;
                float y11 = acc[j][3] + bb1;
                *(float2*)&out_y[(size_t)r0g * CC + c]       = make_float2(y00, y01);
                *(float2*)&out_y[(size_t)(r0g + 8) * CC + c] = make_float2(y10, y11);
                s  += y00 + y01 + y10 + y11;
                s2 += y00 * y00 + y01 * y01 + y10 * y10 + y11 * y11;
            }
            #pragma unroll
            for (int o = 16; o > 0; o >>= 1) {
                s  += __shfl_xor_sync(0xffffffffu, s,  o);
                s2 += __shfl_xor_sync(0xffffffffu, s2, o);
            }
            if (lane == 0) {
                int g = (nbase >> 4) + gj;
                atomicAdd(&s_gsum[g], s);
                atomicAdd(&s_gsqs[g], s2);
            }
        }
    }
    __syncthreads();
    if (tid < GROUPS) {
        atomicAdd(&g_sum[layer][b * GROUPS + tid], s_gsum[tid]);
        atomicAdd(&g_sqs[layer][b * GROUPS + tid], s_gsqs[tid]);
    }
}

// ---------------------------------------------------------------------------
// Finalize: out = leaky(GN3(y3))
// ---------------------------------------------------------------------------
__global__ void finalize_kernel(const float* __restrict__ in_y,
                                const float* __restrict__ gamma,
                                const float* __restrict__ beta,
                                float* __restrict__ out) {
    int f  = blockIdx.x * blockDim.x + threadIdx.x;
    int e  = f * 4;
    int c4 = e & (CC - 1);
    int row = e >> 7;
    int b  = row >> 13;
    int g  = c4 >> 4;
    float s  = g_sum[2][b * GROUPS + g];
    float s2 = g_sqs[2][b * GROUPS + g];
    float m  = s * CNT_INV;
    float v  = s2 * CNT_INV - m * m;
    float rs = rsqrtf(v + 1e-5f);
    float4 x = *(const float4*)&in_y[e];
    float4 o;
    o.x = leaky((x.x - m) * rs * gamma[c4 + 0] + beta[c4 + 0]);
    o.y = leaky((x.y - m) * rs * gamma[c4 + 1] + beta[c4 + 1]);
    o.z = leaky((x.z - m) * rs * gamma[c4 + 2] + beta[c4 + 2]);
    o.w = leaky((x.w - m) * rs * gamma[c4 + 3] + beta[c4 + 3]);
    *(float4*)&out[e] = o;
}

// ---------------------------------------------------------------------------
extern "C" void kernel_launch(void* const* d_in, const int* in_sizes, int n_in,
                              void* d_out, int out_size) {
    const float* q_feats  = (const float*)d_in[0];
    const float* s_feats  = (const float*)d_in[1];
    const float* q_points = (const float*)d_in[2];
    const float* s_points = (const float*)d_in[3];
    const int*   nbr_idx  = (const int*)  d_in[4];
    const float* W1 = (const float*)d_in[5];
    const float* b1 = (const float*)d_in[6];
    const float* g1 = (const float*)d_in[7];
    const float* be1 = (const float*)d_in[8];
    const float* W2 = (const float*)d_in[9];
    const float* b2 = (const float*)d_in[10];
    const float* g2 = (const float*)d_in[11];
    const float* be2 = (const float*)d_in[12];
    const float* W3 = (const float*)d_in[13];
    const float* b3 = (const float*)d_in[14];
    const float* g3 = (const float*)d_in[15];
    const float* be3 = (const float*)d_in[16];
    float* out = (float*)d_out;

    float *buf0 = nullptr, *buf1 = nullptr;
    cudaGetSymbolAddress((void**)&buf0, g_buf0);
    cudaGetSymbolAddress((void**)&buf1, g_buf1);

    prep1_kernel<<<(3 * CC * CC + THREADS - 1) / THREADS, THREADS>>>(W1, W2, W3);
    prep2_kernel<<<6, THREADS, SMEM_P2>>>();

    const int nblk = NROWS / TROWS;   // 512
    layer_kernel<0><<<nblk, THREADS, SMEM_DYN>>>(
        nullptr, nullptr, s_feats, q_points, s_points, nbr_idx,
        b1, nullptr, nullptr, 0, buf0);
    layer_kernel<1><<<nblk, THREADS, SMEM_DYN>>>(
        buf0, nullptr, nullptr, nullptr, nullptr, nullptr,
        b2, g1, be1, 1, buf1);
    layer_kernel<2><<<nblk, THREADS, SMEM_DYN>>>(
        buf1, q_feats, nullptr, nullptr, nullptr, nullptr,
        b3, g2, be2, 2, buf0);
    finalize_kernel<<<(NROWS * CC / 4) / THREADS, THREADS>>>(buf0, g3, be3, out);
}

// round 7
// speedup vs baseline: 2.4728x; 1.1717x over previous
#include <cuda_runtime.h>
#include <cuda_bf16.h>
#include <cstdint>

// Problem constants
#define CC      128
#define GROUPS  8
#define NB      4
#define NN      8192
#define MM      32768
#define KNN     16
#define NROWS   (NB*NN)
#define TROWS   64                   // rows per CTA tile
#define THREADS 256
#define CNT_INV (1.0f/131072.0f)
#define APAD    136                  // padded bf16 row stride (272B -> conflict-free ldmatrix)

// layer-kernel smem: A tiles only
#define SM_AH   0
#define SM_AL   (TROWS*APAD*2)             // 17408
#define SMEM_DYN (2*TROWS*APAD*2)          // 34816

// prep smem: one 128xAPAD bf16 tile
#define SMEM_P  (CC*APAD*2)                // 34816

// Scratch (device globals; no cudaMalloc allowed)
__device__ __align__(16) uint4 g_Wfrag[3][2][8][8][32];    // [layer][hi/lo][t][nb16][lane]
__device__ float g_sum[3][NB*GROUPS];
__device__ float g_sqs[3][NB*GROUPS];
__device__ float g_buf0[NROWS*CC];
__device__ float g_buf1[NROWS*CC];

// ---------------------------------------------------------------------------
// Helpers (all plain sm_80+ features; NO 'a'-gated instructions)
// ---------------------------------------------------------------------------
__device__ __forceinline__ uint32_t cvta_smem(const void* p) {
    uint32_t a;
    asm("{ .reg .u64 t; cvta.to.shared.u64 t, %1; cvt.u32.u64 %0, t; }"
        : "=r"(a) : "l"(p));
    return a;
}
__device__ __forceinline__ void ldmx4(uint32_t addr, uint32_t r[4]) {
    asm volatile("ldmatrix.sync.aligned.m8n8.x4.shared.b16 {%0,%1,%2,%3}, [%4];"
        : "=r"(r[0]), "=r"(r[1]), "=r"(r[2]), "=r"(r[3]) : "r"(addr));
}
__device__ __forceinline__ void mma16816(float d[4], const uint32_t a[4],
                                         uint32_t b0, uint32_t b1) {
    asm volatile(
        "mma.sync.aligned.m16n8k16.row.col.f32.bf16.bf16.f32 "
        "{%0,%1,%2,%3}, {%4,%5,%6,%7}, {%8,%9}, {%0,%1,%2,%3};"
        : "+f"(d[0]), "+f"(d[1]), "+f"(d[2]), "+f"(d[3])
        : "r"(a[0]), "r"(a[1]), "r"(a[2]), "r"(a[3]), "r"(b0), "r"(b1));
}
#define STS16(a, v) \
    asm volatile("st.shared.b16 [%0], %1;" :: "r"(a), "h"(v) : "memory")
#define STS64(a, x, y) \
    asm volatile("st.shared.v2.b32 [%0], {%1,%2};" :: "r"(a), "r"(x), "r"(y) : "memory")

__device__ __forceinline__ float leaky(float h) { return h >= 0.0f ? h : 0.1f * h; }

// ---------------------------------------------------------------------------
// prep: zero stats; per block (layer l, half h): split W^T into smem bf16 tile,
// then fragmentize via the exact ldmatrix sequence the GEMM uses. 6 blocks.
// ---------------------------------------------------------------------------
__global__ void prep_kernel(const float* __restrict__ W1,
                            const float* __restrict__ W2,
                            const float* __restrict__ W3) {
    extern __shared__ __align__(16) char smem[];
    const int tid  = threadIdx.x;
    const int wid  = tid >> 5;
    const int lane = tid & 31;
    const int l = blockIdx.x >> 1;
    const int h = blockIdx.x & 1;
    const uint32_t sb = cvta_smem(smem);

    if (blockIdx.x == 0) {
        if (tid < 96)        { g_sum[tid / 32][tid % 32] = 0.0f; }
        else if (tid < 192)  { int u = tid - 96; g_sqs[u / 32][u % 32] = 0.0f; }
    }

    const float* W = (l == 0) ? W1 : ((l == 1) ? W2 : W3);

    // coalesced read of W[k][n], split, scatter bf16 to smem[n*APAD + k]
    #pragma unroll
    for (int t = 0; t < 64; t++) {
        int idx = tid + t * THREADS;       // 16384 elements
        int k   = idx >> 7;
        int n   = idx & 127;
        float v = W[idx];
        __nv_bfloat16 hi = __float2bfloat16(v);
        __nv_bfloat16 val = h == 0 ? hi : __float2bfloat16(v - __bfloat162float(hi));
        STS16(sb + (uint32_t)(n * APAD + k) * 2, __bfloat16_as_ushort(val));
    }
    __syncthreads();

    // 64 jobs: (t, nb16); 8 per warp. Same lane addressing as the GEMM.
    const uint32_t lrow = (uint32_t)((lane & 7) + ((lane >> 4) << 3));
    const uint32_t lcol = (uint32_t)(lane & 8) << 1;
    #pragma unroll
    for (int i = 0; i < 8; i++) {
        int job  = wid * 8 + i;
        int t    = job & 7;
        int nb   = job >> 3;
        uint32_t addr = sb + (((uint32_t)(nb * 16) + lrow) * APAD) * 2 + lcol
                      + (uint32_t)t * 32;
        uint32_t r[4];
        ldmx4(addr, r);
        g_Wfrag[l][h][t][nb][lane] = make_uint4(r[0], r[1], r[2], r[3]);
    }
}

// ---------------------------------------------------------------------------
// Fused layer kernel: 64-row tile, HMMA bf16 3-term-split GEMM.
// B comes from precomputed register fragments in global (L1-shared across CTAs).
// MODE 0: x = IDW gather   MODE 1: x = leaky(GN(prev))   MODE 2: +resid
// ---------------------------------------------------------------------------
template <int MODE>
__global__ __launch_bounds__(THREADS, 4)
void layer_kernel(const float* __restrict__ in_y,
                  const float* __restrict__ resid,
                  const float* __restrict__ s_feats,
                  const float* __restrict__ q_points,
                  const float* __restrict__ s_points,
                  const int*   __restrict__ nbr_idx,
                  const float* __restrict__ bias,
                  const float* __restrict__ gamma_prev,
                  const float* __restrict__ beta_prev,
                  int layer,
                  float* __restrict__ out_y) {
    extern __shared__ __align__(16) char smem[];
    __shared__ float s_ms[GROUPS], s_rs[GROUPS];
    __shared__ float s_gb[2 * CC];
    __shared__ float s_gsum[GROUPS], s_gsqs[GROUPS];

    const int tid  = threadIdx.x;
    const int wid  = tid >> 5;
    const int lane = tid & 31;
    const int row0 = blockIdx.x * TROWS;
    const int b    = row0 >> 13;

    const uint32_t sb = cvta_smem(smem);

    if (tid < GROUPS) { s_gsum[tid] = 0.0f; s_gsqs[tid] = 0.0f; }

    if (MODE != 0) {
        if (tid < GROUPS) {
            float s  = g_sum[layer - 1][b * GROUPS + tid];
            float s2 = g_sqs[layer - 1][b * GROUPS + tid];
            float m  = s * CNT_INV;
            float v  = s2 * CNT_INV - m * m;
            s_ms[tid] = m;
            s_rs[tid] = rsqrtf(v + 1e-5f);
        }
        if (tid < CC) { s_gb[tid] = gamma_prev[tid]; s_gb[CC + tid] = beta_prev[tid]; }
        __syncthreads();
    }

    // ---- Stage A: build x rows, split bf16 hi/lo, store (stride APAD) ----
    #pragma unroll
    for (int it = 0; it < 8; it++) {
        int r, c4;
        float4 x;
        if (MODE == 0) {
            r  = wid * 8 + it;
            c4 = lane * 4;
            int n    = (row0 + r) & (NN - 1);
            int base = b * NN + n;
            float qx = q_points[base * 3 + 0];
            float qy = q_points[base * 3 + 1];
            float qz = q_points[base * 3 + 2];
            float wsum = 0.0f;
            x = make_float4(0.f, 0.f, 0.f, 0.f);
            #pragma unroll
            for (int k = 0; k < KNN; k++) {
                const float* sp = s_points + (base * KNN + k) * 3;
                float dx = sp[0] - qx, dy = sp[1] - qy, dz = sp[2] - qz;
                float d2 = dx * dx + dy * dy + dz * dz;
                float w = 1.0f / (d2 + 1e-8f);
                wsum += w;
                int id = nbr_idx[base * KNN + k];
                const float4* fr = (const float4*)(s_feats + ((size_t)(b * MM + id)) * CC);
                float4 v = fr[lane];
                x.x += w * v.x; x.y += w * v.y;
                x.z += w * v.z; x.w += w * v.w;
            }
            float inv = 1.0f / wsum;
            x.x *= inv; x.y *= inv; x.z *= inv; x.w *= inv;
        } else {
            int f = tid + it * THREADS;
            r  = f >> 5;
            c4 = (f & 31) * 4;
            int g = c4 >> 4;
            float m = s_ms[g], rs = s_rs[g];
            float4 v = *(const float4*)&in_y[(size_t)(row0 + r) * CC + c4];
            x.x = leaky((v.x - m) * rs * s_gb[c4 + 0] + s_gb[CC + c4 + 0]);
            x.y = leaky((v.y - m) * rs * s_gb[c4 + 1] + s_gb[CC + c4 + 1]);
            x.z = leaky((v.z - m) * rs * s_gb[c4 + 2] + s_gb[CC + c4 + 2]);
            x.w = leaky((v.w - m) * rs * s_gb[c4 + 3] + s_gb[CC + c4 + 3]);
            if (MODE == 2) {
                float4 q = *(const float4*)&resid[(size_t)(row0 + r) * CC + c4];
                x.x += q.x; x.y += q.y; x.z += q.z; x.w += q.w;
            }
        }
        __nv_bfloat16 h0 = __float2bfloat16(x.x);
        __nv_bfloat16 h1 = __float2bfloat16(x.y);
        __nv_bfloat16 h2 = __float2bfloat16(x.z);
        __nv_bfloat16 h3 = __float2bfloat16(x.w);
        __nv_bfloat16 l0 = __float2bfloat16(x.x - __bfloat162float(h0));
        __nv_bfloat16 l1 = __float2bfloat16(x.y - __bfloat162float(h1));
        __nv_bfloat16 l2 = __float2bfloat16(x.z - __bfloat162float(h2));
        __nv_bfloat16 l3 = __float2bfloat16(x.w - __bfloat162float(h3));
        uint32_t ha = (uint32_t)__bfloat16_as_ushort(h0) | ((uint32_t)__bfloat16_as_ushort(h1) << 16);
        uint32_t hb = (uint32_t)__bfloat16_as_ushort(h2) | ((uint32_t)__bfloat16_as_ushort(h3) << 16);
        uint32_t la = (uint32_t)__bfloat16_as_ushort(l0) | ((uint32_t)__bfloat16_as_ushort(l1) << 16);
        uint32_t lb = (uint32_t)__bfloat16_as_ushort(l2) | ((uint32_t)__bfloat16_as_ushort(l3) << 16);
        uint32_t off = (uint32_t)(r * APAD + c4) * 2;
        STS64(sb + SM_AH + off, ha, hb);
        STS64(sb + SM_AL + off, la, lb);
    }
    __syncthreads();

    // ---- HMMA GEMM: warp tile m16 x n64, 3-term split; B frags via LDG ----
    const int mbase = (wid & 3) * 16;
    const int nb0   = (wid >> 2) * 4;     // first n16 fragment index

    float acc[8][4];
    #pragma unroll
    for (int j = 0; j < 8; j++)
        #pragma unroll
        for (int q = 0; q < 4; q++) acc[j][q] = 0.0f;

    const uint32_t aoff = sb + SM_AH +
        (uint32_t)(((mbase + (lane & 15)) * APAD + ((lane >> 4) << 3)) << 1);

    const uint4* __restrict__ wfh = &g_Wfrag[layer][0][0][0][lane];
    const uint4* __restrict__ wfl = &g_Wfrag[layer][1][0][0][lane];

    #pragma unroll
    for (int t = 0; t < 8; t++) {
        const uint32_t ka = (uint32_t)t * 32;
        uint32_t ah[4], al[4];
        ldmx4(aoff + ka, ah);
        ldmx4(aoff + ka + SM_AL, al);
        #pragma unroll
        for (int p = 0; p < 4; p++) {
            const int fidx = (t * 8 + nb0 + p) * 32;
            uint4 bh = __ldg(wfh + fidx);
            uint4 bl = __ldg(wfl + fidx);
            float* a0 = acc[2 * p];
            float* a1 = acc[2 * p + 1];
            mma16816(a0, ah, bh.x, bh.y);
            mma16816(a0, al, bh.x, bh.y);
            mma16816(a0, ah, bl.x, bl.y);
            mma16816(a1, ah, bh.z, bh.w);
            mma16816(a1, al, bh.z, bh.w);
            mma16816(a1, ah, bl.z, bl.w);
        }
    }

    // ---- Epilogue: bias + store from fragments, warp-reduced stats ----
    {
        const int r0g   = row0 + mbase + (lane >> 2);
        const int nbase = (wid >> 2) * 64;
        #pragma unroll
        for (int gj = 0; gj < 4; gj++) {
            float s = 0.0f, s2 = 0.0f;
            #pragma unroll
            for (int jj = 0; jj < 2; jj++) {
                int j = 2 * gj + jj;
                int c = nbase + 8 * j + (lane & 3) * 2;
                float bb0 = __ldg(&bias[c]);
                float bb1 = __ldg(&bias[c + 1]);
                float y00 = acc[j][0] + bb0;
                float y01 = acc[j][1] + bb1;
                float y10 = acc[j][2] + bb0;
                float y11 = acc[j][3] + bb1;
                *(float2*)&out_y[(size_t)r0g * CC + c]       = make_float2(y00, y01);
                *(float2*)&out_y[(size_t)(r0g + 8) * CC + c] = make_float2(y10, y11);
                s  += y00 + y01 + y10 + y11;
                s2 += y00 * y00 + y01 * y01 + y10 * y10 + y11 * y11;
            }
            #pragma unroll
            for (int o = 16; o > 0; o >>= 1) {
                s  += __shfl_xor_sync(0xffffffffu, s,  o);
                s2 += __shfl_xor_sync(0xffffffffu, s2, o);
            }
            if (lane == 0) {
                int g = (nbase >> 4) + gj;
                atomicAdd(&s_gsum[g], s);
                atomicAdd(&s_gsqs[g], s2);
            }
        }
    }
    __syncthreads();
    if (tid < GROUPS) {
        atomicAdd(&g_sum[layer][b * GROUPS + tid], s_gsum[tid]);
        atomicAdd(&g_sqs[layer][b * GROUPS + tid], s_gsqs[tid]);
    }
}

// ---------------------------------------------------------------------------
// Finalize: out = leaky(GN3(y3))
// ---------------------------------------------------------------------------
__global__ void finalize_kernel(const float* __restrict__ in_y,
                                const float* __restrict__ gamma,
                                const float* __restrict__ beta,
                                float* __restrict__ out) {
    int f  = blockIdx.x * blockDim.x + threadIdx.x;
    int e  = f * 4;
    int c4 = e & (CC - 1);
    int row = e >> 7;
    int b  = row >> 13;
    int g  = c4 >> 4;
    float s  = g_sum[2][b * GROUPS + g];
    float s2 = g_sqs[2][b * GROUPS + g];
    float m  = s * CNT_INV;
    float v  = s2 * CNT_INV - m * m;
    float rs = rsqrtf(v + 1e-5f);
    float4 x = *(const float4*)&in_y[e];
    float4 o;
    o.x = leaky((x.x - m) * rs * gamma[c4 + 0] + beta[c4 + 0]);
    o.y = leaky((x.y - m) * rs * gamma[c4 + 1] + beta[c4 + 1]);
    o.z = leaky((x.z - m) * rs * gamma[c4 + 2] + beta[c4 + 2]);
    o.w = leaky((x.w - m) * rs * gamma[c4 + 3] + beta[c4 + 3]);
    *(float4*)&out[e] = o;
}

// ---------------------------------------------------------------------------
extern "C" void kernel_launch(void* const* d_in, const int* in_sizes, int n_in,
                              void* d_out, int out_size) {
    const float* q_feats  = (const float*)d_in[0];
    const float* s_feats  = (const float*)d_in[1];
    const float* q_points = (const float*)d_in[2];
    const float* s_points = (const float*)d_in[3];
    const int*   nbr_idx  = (const int*)  d_in[4];
    const float* W1 = (const float*)d_in[5];
    const float* b1 = (const float*)d_in[6];
    const float* g1 = (const float*)d_in[7];
    const float* be1 = (const float*)d_in[8];
    const float* W2 = (const float*)d_in[9];
    const float* b2 = (const float*)d_in[10];
    const float* g2 = (const float*)d_in[11];
    const float* be2 = (const float*)d_in[12];
    const float* W3 = (const float*)d_in[13];
    const float* b3 = (const float*)d_in[14];
    const float* g3 = (const float*)d_in[15];
    const float* be3 = (const float*)d_in[16];
    float* out = (float*)d_out;

    float *buf0 = nullptr, *buf1 = nullptr;
    cudaGetSymbolAddress((void**)&buf0, g_buf0);
    cudaGetSymbolAddress((void**)&buf1, g_buf1);

    prep_kernel<<<6, THREADS, SMEM_P>>>(W1, W2, W3);

    const int nblk = NROWS / TROWS;   // 512
    layer_kernel<0><<<nblk, THREADS, SMEM_DYN>>>(
        nullptr, nullptr, s_feats, q_points, s_points, nbr_idx,
        b1, nullptr, nullptr, 0, buf0);
    layer_kernel<1><<<nblk, THREADS, SMEM_DYN>>>(
        buf0, nullptr, nullptr, nullptr, nullptr, nullptr,
        b2, g1, be1, 1, buf1);
    layer_kernel<2><<<nblk, THREADS, SMEM_DYN>>>(
        buf1, q_feats, nullptr, nullptr, nullptr, nullptr,
        b3, g2, be2, 2, buf0);
    finalize_kernel<<<(NROWS * CC / 4) / THREADS, THREADS>>>(buf0, g3, be3, out);
}

// round 10
// speedup vs baseline: 3.3199x; 1.3426x over previous
#include <cuda_runtime.h>
#include <cuda_bf16.h>
#include <cstdint>

// Problem constants
#define CC      128
#define GROUPS  8
#define NB      4
#define NN      8192
#define MM      32768
#define KNN     16
#define NROWS   (NB*NN)
#define TROWS   64                   // rows per CTA tile
#define THREADS 256
#define CNT_INV (1.0f/131072.0f)
#define APAD    136                  // padded bf16 row stride (272B -> conflict-free ldmatrix)

// layer-kernel smem: A tiles only
#define SM_AH   0
#define SM_AL   (TROWS*APAD*2)             // 17408
#define SMEM_DYN (2*TROWS*APAD*2)          // 34816

// prep smem: one 128xAPAD bf16 tile
#define SMEM_P  (CC*APAD*2)                // 34816

// Scratch (device globals; no cudaMalloc allowed)
__device__ __align__(16) uint4 g_Wfrag[3][2][8][8][32];    // [layer][hi/lo][t][nb16][lane]
__device__ float g_sum[3][NB*GROUPS];
__device__ float g_sqs[3][NB*GROUPS];
__device__ float g_buf0[NROWS*CC];
__device__ float g_buf1[NROWS*CC];

// ---------------------------------------------------------------------------
// Helpers (all plain sm_80+ features; NO 'a'-gated instructions)
// ---------------------------------------------------------------------------
__device__ __forceinline__ uint32_t cvta_smem(const void* p) {
    uint32_t a;
    asm("{ .reg .u64 t; cvta.to.shared.u64 t, %1; cvt.u32.u64 %0, t; }"
        : "=r"(a) : "l"(p));
    return a;
}
__device__ __forceinline__ void ldmx4(uint32_t addr, uint32_t r[4]) {
    asm volatile("ldmatrix.sync.aligned.m8n8.x4.shared.b16 {%0,%1,%2,%3}, [%4];"
        : "=r"(r[0]), "=r"(r[1]), "=r"(r[2]), "=r"(r[3]) : "r"(addr));
}
__device__ __forceinline__ void mma16816(float d[4], const uint32_t a[4],
                                         uint32_t b0, uint32_t b1) {
    asm volatile(
        "mma.sync.aligned.m16n8k16.row.col.f32.bf16.bf16.f32 "
        "{%0,%1,%2,%3}, {%4,%5,%6,%7}, {%8,%9}, {%0,%1,%2,%3};"
        : "+f"(d[0]), "+f"(d[1]), "+f"(d[2]), "+f"(d[3])
        : "r"(a[0]), "r"(a[1]), "r"(a[2]), "r"(a[3]), "r"(b0), "r"(b1));
}
#define STS16(a, v) \
    asm volatile("st.shared.b16 [%0], %1;" :: "r"(a), "h"(v) : "memory")
#define STS64(a, x, y) \
    asm volatile("st.shared.v2.b32 [%0], {%1,%2};" :: "r"(a), "r"(x), "r"(y) : "memory")

__device__ __forceinline__ float leaky(float h) { return h >= 0.0f ? h : 0.1f * h; }

// ---------------------------------------------------------------------------
// prep: zero stats; per block (layer l, half h): split W^T into smem bf16 tile,
// then fragmentize via the exact ldmatrix sequence the GEMM uses. 6 blocks.
// ---------------------------------------------------------------------------
__global__ void prep_kernel(const float* __restrict__ W1,
                            const float* __restrict__ W2,
                            const float* __restrict__ W3) {
    extern __shared__ __align__(16) char smem[];
    const int tid  = threadIdx.x;
    const int wid  = tid >> 5;
    const int lane = tid & 31;
    const int l = blockIdx.x >> 1;
    const int h = blockIdx.x & 1;
    const uint32_t sb = cvta_smem(smem);

    if (blockIdx.x == 0) {
        if (tid < 96)        { g_sum[tid / 32][tid % 32] = 0.0f; }
        else if (tid < 192)  { int u = tid - 96; g_sqs[u / 32][u % 32] = 0.0f; }
    }

    const float* W = (l == 0) ? W1 : ((l == 1) ? W2 : W3);

    // coalesced read of W[k][n], split, scatter bf16 to smem[n*APAD + k]
    #pragma unroll
    for (int t = 0; t < 64; t++) {
        int idx = tid + t * THREADS;       // 16384 elements
        int k   = idx >> 7;
        int n   = idx & 127;
        float v = W[idx];
        __nv_bfloat16 hi = __float2bfloat16(v);
        __nv_bfloat16 val = h == 0 ? hi : __float2bfloat16(v - __bfloat162float(hi));
        STS16(sb + (uint32_t)(n * APAD + k) * 2, __bfloat16_as_ushort(val));
    }
    __syncthreads();

    // 64 jobs: (t, nb16); 8 per warp. Same lane addressing as the GEMM.
    const uint32_t lrow = (uint32_t)((lane & 7) + ((lane >> 4) << 3));
    const uint32_t lcol = (uint32_t)(lane & 8) << 1;
    #pragma unroll
    for (int i = 0; i < 8; i++) {
        int job  = wid * 8 + i;
        int t    = job & 7;
        int nb   = job >> 3;
        uint32_t addr = sb + (((uint32_t)(nb * 16) + lrow) * APAD) * 2 + lcol
                      + (uint32_t)t * 32;
        uint32_t r[4];
        ldmx4(addr, r);
        g_Wfrag[l][h][t][nb][lane] = make_uint4(r[0], r[1], r[2], r[3]);
    }
}

// ---------------------------------------------------------------------------
// Fused layer kernel: 64-row tile, HMMA bf16 3-term-split GEMM.
// B comes from precomputed register fragments in global (L1-shared across CTAs).
// MODE 0: x = IDW gather (lane-parallel neighbor stage + shuffle broadcast)
// MODE 1: x = leaky(GN(prev))   MODE 2: +resid
// ---------------------------------------------------------------------------
template <int MODE>
__global__ __launch_bounds__(THREADS, 4)
void layer_kernel(const float* __restrict__ in_y,
                  const float* __restrict__ resid,
                  const float* __restrict__ s_feats,
                  const float* __restrict__ q_points,
                  const float* __restrict__ s_points,
                  const int*   __restrict__ nbr_idx,
                  const float* __restrict__ bias,
                  const float* __restrict__ gamma_prev,
                  const float* __restrict__ beta_prev,
                  int layer,
                  float* __restrict__ out_y) {
    extern __shared__ __align__(16) char smem[];
    __shared__ float s_ms[GROUPS], s_rs[GROUPS];
    __shared__ float s_gb[2 * CC];
    __shared__ float s_gsum[GROUPS], s_gsqs[GROUPS];

    const int tid  = threadIdx.x;
    const int wid  = tid >> 5;
    const int lane = tid & 31;
    const int row0 = blockIdx.x * TROWS;
    const int b    = row0 >> 13;

    const uint32_t sb = cvta_smem(smem);

    if (tid < GROUPS) { s_gsum[tid] = 0.0f; s_gsqs[tid] = 0.0f; }

    if (MODE != 0) {
        if (tid < GROUPS) {
            float s  = g_sum[layer - 1][b * GROUPS + tid];
            float s2 = g_sqs[layer - 1][b * GROUPS + tid];
            float m  = s * CNT_INV;
            float v  = s2 * CNT_INV - m * m;
            s_ms[tid] = m;
            s_rs[tid] = rsqrtf(v + 1e-5f);
        }
        if (tid < CC) { s_gb[tid] = gamma_prev[tid]; s_gb[CC + tid] = beta_prev[tid]; }
        __syncthreads();
    }

    // ---- Stage A: build x rows, split bf16 hi/lo, store (stride APAD) ----
    #pragma unroll
    for (int it = 0; it < 8; it++) {
        int r, c4;
        float4 x;
        if (MODE == 0) {
            r  = wid * 8 + it;
            c4 = lane * 4;
            int n    = (row0 + r) & (NN - 1);
            int base = b * NN + n;
            // lane-parallel: lane k<16 owns neighbor k
            float w = 0.0f;
            int   id = 0;
            {
                float qx = q_points[base * 3 + 0];
                float qy = q_points[base * 3 + 1];
                float qz = q_points[base * 3 + 2];
                if (lane < KNN) {
                    const float* sp = s_points + ((size_t)base * KNN + lane) * 3;
                    float dx = sp[0] - qx, dy = sp[1] - qy, dz = sp[2] - qz;
                    w  = 1.0f / (dx * dx + dy * dy + dz * dz + 1e-8f);
                    id = nbr_idx[base * KNN + lane];
                }
            }
            float wsum = w;
            #pragma unroll
            for (int o = 16; o > 0; o >>= 1)
                wsum += __shfl_xor_sync(0xffffffffu, wsum, o);
            float inv = 1.0f / wsum;
            x = make_float4(0.f, 0.f, 0.f, 0.f);
            #pragma unroll
            for (int k = 0; k < KNN; k++) {
                float wk  = __shfl_sync(0xffffffffu, w,  k);
                int   idk = __shfl_sync(0xffffffffu, id, k);
                const float4* fr = (const float4*)(s_feats + ((size_t)(b * MM + idk)) * CC);
                float4 v = fr[lane];
                x.x += wk * v.x; x.y += wk * v.y;
                x.z += wk * v.z; x.w += wk * v.w;
            }
            x.x *= inv; x.y *= inv; x.z *= inv; x.w *= inv;
        } else {
            int f = tid + it * THREADS;
            r  = f >> 5;
            c4 = (f & 31) * 4;
            int g = c4 >> 4;
            float m = s_ms[g], rs = s_rs[g];
            float4 v = *(const float4*)&in_y[(size_t)(row0 + r) * CC + c4];
            x.x = leaky((v.x - m) * rs * s_gb[c4 + 0] + s_gb[CC + c4 + 0]);
            x.y = leaky((v.y - m) * rs * s_gb[c4 + 1] + s_gb[CC + c4 + 1]);
            x.z = leaky((v.z - m) * rs * s_gb[c4 + 2] + s_gb[CC + c4 + 2]);
            x.w = leaky((v.w - m) * rs * s_gb[c4 + 3] + s_gb[CC + c4 + 3]);
            if (MODE == 2) {
                float4 q = *(const float4*)&resid[(size_t)(row0 + r) * CC + c4];
                x.x += q.x; x.y += q.y; x.z += q.z; x.w += q.w;
            }
        }
        __nv_bfloat16 h0 = __float2bfloat16(x.x);
        __nv_bfloat16 h1 = __float2bfloat16(x.y);
        __nv_bfloat16 h2 = __float2bfloat16(x.z);
        __nv_bfloat16 h3 = __float2bfloat16(x.w);
        __nv_bfloat16 l0 = __float2bfloat16(x.x - __bfloat162float(h0));
        __nv_bfloat16 l1 = __float2bfloat16(x.y - __bfloat162float(h1));
        __nv_bfloat16 l2 = __float2bfloat16(x.z - __bfloat162float(h2));
        __nv_bfloat16 l3 = __float2bfloat16(x.w - __bfloat162float(h3));
        uint32_t ha = (uint32_t)__bfloat16_as_ushort(h0) | ((uint32_t)__bfloat16_as_ushort(h1) << 16);
        uint32_t hb = (uint32_t)__bfloat16_as_ushort(h2) | ((uint32_t)__bfloat16_as_ushort(h3) << 16);
        uint32_t la = (uint32_t)__bfloat16_as_ushort(l0) | ((uint32_t)__bfloat16_as_ushort(l1) << 16);
        uint32_t lb = (uint32_t)__bfloat16_as_ushort(l2) | ((uint32_t)__bfloat16_as_ushort(l3) << 16);
        uint32_t off = (uint32_t)(r * APAD + c4) * 2;
        STS64(sb + SM_AH + off, ha, hb);
        STS64(sb + SM_AL + off, la, lb);
    }
    __syncthreads();

    // ---- HMMA GEMM: warp tile m16 x n64, 3-term split; B frags via LDG ----
    const int mbase = (wid & 3) * 16;
    const int nb0   = (wid >> 2) * 4;     // first n16 fragment index

    float acc[8][4];
    #pragma unroll
    for (int j = 0; j < 8; j++)
        #pragma unroll
        for (int q = 0; q < 4; q++) acc[j][q] = 0.0f;

    const uint32_t aoff = sb + SM_AH +
        (uint32_t)(((mbase + (lane & 15)) * APAD + ((lane >> 4) << 3)) << 1);

    const uint4* __restrict__ wfh = &g_Wfrag[layer][0][0][0][lane];
    const uint4* __restrict__ wfl = &g_Wfrag[layer][1][0][0][lane];

    #pragma unroll
    for (int t = 0; t < 8; t++) {
        const uint32_t ka = (uint32_t)t * 32;
        uint32_t ah[4], al[4];
        ldmx4(aoff + ka, ah);
        ldmx4(aoff + ka + SM_AL, al);
        #pragma unroll
        for (int p = 0; p < 4; p++) {
            const int fidx = (t * 8 + nb0 + p) * 32;
            uint4 bh = __ldg(wfh + fidx);
            uint4 bl = __ldg(wfl + fidx);
            float* a0 = acc[2 * p];
            float* a1 = acc[2 * p + 1];
            mma16816(a0, ah, bh.x, bh.y);
            mma16816(a0, al, bh.x, bh.y);
            mma16816(a0, ah, bl.x, bl.y);
            mma16816(a1, ah, bh.z, bh.w);
            mma16816(a1, al, bh.z, bh.w);
            mma16816(a1, ah, bl.z, bl.w);
        }
    }

    // ---- Epilogue: bias + store from fragments, warp-reduced stats ----
    {
        const int r0g   = row0 + mbase + (lane >> 2);
        const int nbase = (wid >> 2) * 64;
        #pragma unroll
        for (int gj = 0; gj < 4; gj++) {
            float s = 0.0f, s2 = 0.0f;
            #pragma unroll
            for (int jj = 0; jj < 2; jj++) {
                int j = 2 * gj + jj;
                int c = nbase + 8 * j + (lane & 3) * 2;
                float bb0 = __ldg(&bias[c]);
                float bb1 = __ldg(&bias[c + 1]);
                float y00 = acc[j][0] + bb0;
                float y01 = acc[j][1] + bb1;
                float y10 = acc[j][2] + bb0;
                float y11 = acc[j][3] + bb1;
                *(float2*)&out_y[(size_t)r0g * CC + c]       = make_float2(y00, y01);
                *(float2*)&out_y[(size_t)(r0g + 8) * CC + c] = make_float2(y10, y11);
                s  += y00 + y01 + y10 + y11;
                s2 += y00 * y00 + y01 * y01 + y10 * y10 + y11 * y11;
            }
            #pragma unroll
            for (int o = 16; o > 0; o >>= 1) {
                s  += __shfl_xor_sync(0xffffffffu, s,  o);
                s2 += __shfl_xor_sync(0xffffffffu, s2, o);
            }
            if (lane == 0) {
                int g = (nbase >> 4) + gj;
                atomicAdd(&s_gsum[g], s);
                atomicAdd(&s_gsqs[g], s2);
            }
        }
    }
    __syncthreads();
    if (tid < GROUPS) {
        atomicAdd(&g_sum[layer][b * GROUPS + tid], s_gsum[tid]);
        atomicAdd(&g_sqs[layer][b * GROUPS + tid], s_gsqs[tid]);
    }
}

// ---------------------------------------------------------------------------
// Finalize: out = leaky(GN3(y3))
// ---------------------------------------------------------------------------
__global__ void finalize_kernel(const float* __restrict__ in_y,
                                const float* __restrict__ gamma,
                                const float* __restrict__ beta,
                                float* __restrict__ out) {
    int f  = blockIdx.x * blockDim.x + threadIdx.x;
    int e  = f * 4;
    int c4 = e & (CC - 1);
    int row = e >> 7;
    int b  = row >> 13;
    int g  = c4 >> 4;
    float s  = g_sum[2][b * GROUPS + g];
    float s2 = g_sqs[2][b * GROUPS + g];
    float m  = s * CNT_INV;
    float v  = s2 * CNT_INV - m * m;
    float rs = rsqrtf(v + 1e-5f);
    float4 x = *(const float4*)&in_y[e];
    float4 o;
    o.x = leaky((x.x - m) * rs * gamma[c4 + 0] + beta[c4 + 0]);
    o.y = leaky((x.y - m) * rs * gamma[c4 + 1] + beta[c4 + 1]);
    o.z = leaky((x.z - m) * rs * gamma[c4 + 2] + beta[c4 + 2]);
    o.w = leaky((x.w - m) * rs * gamma[c4 + 3] + beta[c4 + 3]);
    *(float4*)&out[e] = o;
}

// ---------------------------------------------------------------------------
extern "C" void kernel_launch(void* const* d_in, const int* in_sizes, int n_in,
                              void* d_out, int out_size) {
    const float* q_feats  = (const float*)d_in[0];
    const float* s_feats  = (const float*)d_in[1];
    const float* q_points = (const float*)d_in[2];
    const float* s_points = (const float*)d_in[3];
    const int*   nbr_idx  = (const int*)  d_in[4];
    const float* W1 = (const float*)d_in[5];
    const float* b1 = (const float*)d_in[6];
    const float* g1 = (const float*)d_in[7];
    const float* be1 = (const float*)d_in[8];
    const float* W2 = (const float*)d_in[9];
    const float* b2 = (const float*)d_in[10];
    const float* g2 = (const float*)d_in[11];
    const float* be2 = (const float*)d_in[12];
    const float* W3 = (const float*)d_in[13];
    const float* b3 = (const float*)d_in[14];
    const float* g3 = (const float*)d_in[15];
    const float* be3 = (const float*)d_in[16];
    float* out = (float*)d_out;

    float *buf0 = nullptr, *buf1 = nullptr;
    cudaGetSymbolAddress((void**)&buf0, g_buf0);
    cudaGetSymbolAddress((void**)&buf1, g_buf1);

    prep_kernel<<<6, THREADS, SMEM_P>>>(W1, W2, W3);

    const int nblk = NROWS / TROWS;   // 512
    layer_kernel<0><<<nblk, THREADS, SMEM_DYN>>>(
        nullptr, nullptr, s_feats, q_points, s_points, nbr_idx,
        b1, nullptr, nullptr, 0, buf0);
    layer_kernel<1><<<nblk, THREADS, SMEM_DYN>>>(
        buf0, nullptr, nullptr, nullptr, nullptr, nullptr,
        b2, g1, be1, 1, buf1);
    layer_kernel<2><<<nblk, THREADS, SMEM_DYN>>>(
        buf1, q_feats, nullptr, nullptr, nullptr, nullptr,
        b3, g2, be2, 2, buf0);
    finalize_kernel<<<(NROWS * CC / 4) / THREADS, THREADS>>>(buf0, g3, be3, out);
}